// round 7
// baseline (speedup 1.0000x reference)
#include <cuda_runtime.h>
#include <cuda_fp16.h>

// ---------------- problem constants ----------------
#define NSENT   4000
#define LSEQ    128
#define VOCAB   50002
#define VEC_DIM 50
#define POS_DIM 5
#define EMB     60
#define HID     230
#define PADC    240            // HID padded to 240
#define ROWW    (3*PADC)       // 720 entries per table row (3 kernel taps)
#define ROWB    (ROWW*2)       // row stride in bytes (fp16)
#define KPAD    64             // VEC_DIM padded to 64 for mma (4 k-steps of 16)
#define NCOLT   (ROWW/8)       // 90 col-tiles of 8
#define NROWT   ((VOCAB+15)/16)// 3126 row-tiles of 16
#define SDSTR   728            // s_D row stride in halfs (16B-aligned, conflict-free)
#define NPOS    201
#define NBAG    500
#define NREL    25

// ---------------- device scratch (static; no runtime allocation) ----------------
__device__ __half g_Bt [ROWW * KPAD];              // B transposed: [720 cols][64 k] fp16
__device__ __half g_Tw [(size_t)VOCAB * ROWW];     // word projection table (fp16, ~72 MB)
__device__ __half g_Tp1[NPOS * ROWW];              // pos1 projection table (fp16)
__device__ __half g_Tp2[NPOS * ROWW];              // pos2 projection table (fp16)
__device__ float  g_H  [NSENT * PADC];             // sentence encodings

// ---------------- helpers ----------------
__device__ __forceinline__ uint2 ldu2b(const char* p) {
    return *reinterpret_cast<const uint2*>(p);
}
__device__ __forceinline__ __half2 h2lo(uint2 u) { return *reinterpret_cast<__half2*>(&u.x); }
__device__ __forceinline__ __half2 h2hi(uint2 u) { return *reinterpret_cast<__half2*>(&u.y); }

// ---------------- kernel 1: build fp16 transposed weight matrix g_Bt ----------------
__global__ void k_prep_Bt(const float* __restrict__ conv_w) {
    int i = blockIdx.x * blockDim.x + threadIdx.x;
    if (i >= ROWW * KPAD) return;
    int n = i >> 6;            // 0..719
    int k = i & 63;
    int tap = n / PADC;
    int c = n - tap * PADC;
    float v = (c < HID && k < VEC_DIM) ? conv_w[(c * EMB + k) * 3 + tap] : 0.f;
    g_Bt[i] = __float2half_rn(v);
}

// ---------------- kernel 2: tiny pos tables (K=5, fp16 out) ----------------
__global__ void k_pos_tables(const float* __restrict__ p1e,
                             const float* __restrict__ p2e,
                             const float* __restrict__ conv_w) {
    int p = blockIdx.x;        // 0..200
    int r = threadIdx.x;       // 0..719
    int k = r / PADC;
    int c = r - k * PADC;
    float a1 = 0.f, a2 = 0.f;
    if (c < HID) {
        #pragma unroll
        for (int e = 0; e < POS_DIM; e++) {
            float w1 = conv_w[(c * EMB + VEC_DIM + e) * 3 + k];
            float w2 = conv_w[(c * EMB + VEC_DIM + POS_DIM + e) * 3 + k];
            a1 = fmaf(p1e[p * POS_DIM + e], w1, a1);
            a2 = fmaf(p2e[p * POS_DIM + e], w2, a2);
        }
    }
    g_Tp1[p * ROWW + r] = __float2half_rn(a1);
    g_Tp2[p * ROWW + r] = __float2half_rn(a2);
}

// ---------------- kernel 3: word table build via mma.sync + smem-staged stores ----------------
__global__ __launch_bounds__(256) void k_build_word(const float* __restrict__ word_emb) {
    __shared__ __half s_A[16 * 66];
    __shared__ __half s_D[16 * SDSTR];              // staged output strip (~23 KB)
    int row0 = blockIdx.x * 16;
    int tid  = threadIdx.x;

    for (int i = tid; i < 16 * 64; i += 256) {
        int r = i >> 6, k = i & 63;
        int gr = row0 + r;
        float v = (gr < VOCAB && k < VEC_DIM) ? word_emb[gr * VEC_DIM + k] : 0.f;
        s_A[r * 66 + k] = __float2half_rn(v);
    }
    __syncthreads();

    int warp = tid >> 5, lane = tid & 31;
    int g = lane >> 2, t = lane & 3;

    unsigned uA[4][4];
    #pragma unroll
    for (int ks = 0; ks < 4; ks++) {
        int k0 = ks * 16;
        uA[ks][0] = *reinterpret_cast<unsigned*>(&s_A[ g      * 66 + k0 + 2*t    ]);
        uA[ks][1] = *reinterpret_cast<unsigned*>(&s_A[(g + 8) * 66 + k0 + 2*t    ]);
        uA[ks][2] = *reinterpret_cast<unsigned*>(&s_A[ g      * 66 + k0 + 2*t + 8]);
        uA[ks][3] = *reinterpret_cast<unsigned*>(&s_A[(g + 8) * 66 + k0 + 2*t + 8]);
    }

    for (int ct = warp; ct < NCOLT; ct += 8) {
        int n0 = ct * 8;
        float c0 = 0.f, c1 = 0.f, c2 = 0.f, c3 = 0.f;
        #pragma unroll
        for (int ks = 0; ks < 4; ks++) {
            int k0 = ks * 16;
            const __half* bp = g_Bt + (n0 + g) * KPAD + k0 + 2*t;
            unsigned b0 = *reinterpret_cast<const unsigned*>(bp);
            unsigned b1 = *reinterpret_cast<const unsigned*>(bp + 8);
            asm volatile(
                "mma.sync.aligned.m16n8k16.row.col.f32.f16.f16.f32 "
                "{%0,%1,%2,%3}, {%4,%5,%6,%7}, {%8,%9}, {%0,%1,%2,%3};"
                : "+f"(c0), "+f"(c1), "+f"(c2), "+f"(c3)
                : "r"(uA[ks][0]), "r"(uA[ks][1]), "r"(uA[ks][2]), "r"(uA[ks][3]),
                  "r"(b0), "r"(b1));
        }
        int col = n0 + 2*t;
        *reinterpret_cast<__half2*>(&s_D[ g      * SDSTR + col]) = __floats2half2_rn(c0, c1);
        *reinterpret_cast<__half2*>(&s_D[(g + 8) * SDSTR + col]) = __floats2half2_rn(c2, c3);
    }
    __syncthreads();

    // coalesced copy-out: 16 rows x 90 uint4 (16B) per row
    int nrow = VOCAB - row0;  if (nrow > 16) nrow = 16;
    for (int i = tid; i < nrow * 90; i += 256) {
        int r = i / 90, u = i - r * 90;
        uint4 val = *reinterpret_cast<uint4*>(&s_D[r * SDSTR + u * 8]);
        *reinterpret_cast<uint4*>(&g_Tw[(size_t)(row0 + r) * ROWW + u * 8]) = val;
    }
}

// ---------------- kernel 4: main fused conv-via-gather + maxpool + relu ----------------
// half2 math; word loads (L2-miss path) prefetched 1 iteration ahead, pos loads
// (L1-hot) just-in-time. Small buffer -> 48 regs -> 10 CTAs/SM.
__global__ __launch_bounds__(128, 10) void k_main(const int* __restrict__ X,
                                                  const int* __restrict__ P1,
                                                  const int* __restrict__ P2,
                                                  const float* __restrict__ conv_b) {
    __shared__ int   s_off[2][3][LSEQ + 1];   // precomputed BYTE offsets (+1 dummy token)
    __shared__ float s_b[PADC];
    int tid = threadIdx.x;
    int grp = tid >> 6, tc = tid & 63;
    int sent0 = blockIdx.x * 2;

    for (int i = tid; i < 2 * LSEQ; i += 128) {
        int g = i >> 7, t = i & (LSEQ - 1);
        int s = sent0 + g;
        s_off[g][0][t] = X [s * LSEQ + t] * ROWB;
        s_off[g][1][t] = P1[s * LSEQ + t] * ROWB;
        s_off[g][2][t] = P2[s * LSEQ + t] * ROWB;
    }
    if (tid < 2) {                          // dummy token for prefetch overrun
        s_off[tid][0][LSEQ] = 0;
        s_off[tid][1][LSEQ] = 0;
        s_off[tid][2][LSEQ] = 0;
    }
    for (int i = tid; i < PADC; i += 128) s_b[i] = (i < HID) ? conv_b[i] : 0.f;
    __syncthreads();

    if (tc >= 60) return;
    int cb = tc * 8;                        // channel byte offset within row

    const int* ow = s_off[grp][0];
    const int* o1 = s_off[grp][1];
    const int* o2 = s_off[grp][2];
    const char* baseW = (const char*)g_Tw  + cb;
    const char* base1 = (const char*)g_Tp1 + cb;
    const char* base2 = (const char*)g_Tp2 + cb;

    __half2 maxA  = __float2half2_rn(-60000.f), maxB = maxA;
    __half2 pendA = __float2half2_rn(-16384.f), pendB = pendA;  // absorbs t=0 max-update
    __half2 prevA = __float2half2_rn(0.f),      prevB = prevA;

    // prologue: word loads for t=0
    const char* rw0 = baseW + ow[0];
    uint2 w0 = ldu2b(rw0);  uint2 w1 = ldu2b(rw0 + 2*PADC);  uint2 w2 = ldu2b(rw0 + 4*PADC);

    #pragma unroll 2
    for (int t = 0; t < LSEQ; t++) {
        // pos loads for t (L1-hot, short latency)
        const char* r1 = base1 + o1[t];
        const char* r2 = base2 + o2[t];
        uint2 q0 = ldu2b(r1);  uint2 q1 = ldu2b(r1 + 2*PADC);  uint2 q2 = ldu2b(r1 + 4*PADC);
        uint2 v0 = ldu2b(r2);  uint2 v1 = ldu2b(r2 + 2*PADC);  uint2 v2 = ldu2b(r2 + 4*PADC);
        // word prefetch for t+1 (L2-latency path)
        const char* nw = baseW + ow[t + 1];
        uint2 W0 = ldu2b(nw);  uint2 W1 = ldu2b(nw + 2*PADC);  uint2 W2 = ldu2b(nw + 4*PADC);

        __half2 a2A = __hadd2(__hadd2(h2lo(w2), h2lo(q2)), h2lo(v2));
        __half2 a2B = __hadd2(__hadd2(h2hi(w2), h2hi(q2)), h2hi(v2));
        maxA = __hmax2(maxA, __hadd2(pendA, a2A));      // h[t-1]
        maxB = __hmax2(maxB, __hadd2(pendB, a2B));
        __half2 a1A = __hadd2(__hadd2(h2lo(w1), h2lo(q1)), h2lo(v1));
        __half2 a1B = __hadd2(__hadd2(h2hi(w1), h2hi(q1)), h2hi(v1));
        pendA = __hadd2(prevA, a1A);
        pendB = __hadd2(prevB, a1B);
        prevA = __hadd2(__hadd2(h2lo(w0), h2lo(q0)), h2lo(v0));
        prevB = __hadd2(__hadd2(h2hi(w0), h2hi(q0)), h2hi(v0));

        w0 = W0; w1 = W1; w2 = W2;
    }
    maxA = __hmax2(maxA, pendA);            // h[L-1] (a2 of pad token = 0)
    maxB = __hmax2(maxB, pendB);

    float2 mA = __half22float2(maxA);
    float2 mB = __half22float2(maxB);
    int s = sent0 + grp;
    int coff = tc * 4;
    g_H[s * PADC + coff + 0] = fmaxf(mA.x + s_b[coff + 0], 0.f);
    g_H[s * PADC + coff + 1] = fmaxf(mA.y + s_b[coff + 1], 0.f);
    g_H[s * PADC + coff + 2] = fmaxf(mB.x + s_b[coff + 2], 0.f);
    g_H[s * PADC + coff + 3] = fmaxf(mB.y + s_b[coff + 3], 0.f);
}

// ---------------- kernel 5: per-bag softmax attention + classifier ----------------
__global__ __launch_bounds__(256) void k_bags(const int* __restrict__ scope,
                                              const int* __restrict__ relation,
                                              const float* __restrict__ rel_w,
                                              const float* __restrict__ rel_b,
                                              float* __restrict__ out) {
    int b = blockIdx.x;
    __shared__ float s_q[HID];
    __shared__ float s_logit[8];
    __shared__ float s_alpha[8];
    __shared__ float s_rep[HID];

    int tid = threadIdx.x;
    int w = tid >> 5, lane = tid & 31;
    int s0 = scope[2 * b], s1 = scope[2 * b + 1];
    int sz = s1 - s0;
    if (sz > 8) sz = 8;
    int rq = relation[b];

    for (int c = tid; c < HID; c += 256) s_q[c] = rel_w[rq * HID + c];
    __syncthreads();

    if (w < 8) {
        float acc = 0.f;
        if (w < sz) {
            const float* hp = g_H + (size_t)(s0 + w) * PADC;
            for (int c = lane; c < HID; c += 32) acc = fmaf(hp[c], s_q[c], acc);
        }
        #pragma unroll
        for (int o = 16; o; o >>= 1) acc += __shfl_xor_sync(0xffffffffu, acc, o);
        if (lane == 0) s_logit[w] = (w < sz) ? acc : -1e30f;
    }
    __syncthreads();

    if (tid == 0) {
        float m = -1e30f;
        for (int i = 0; i < sz; i++) m = fmaxf(m, s_logit[i]);
        float d = 0.f;
        for (int i = 0; i < sz; i++) { float e = expf(s_logit[i] - m); s_alpha[i] = e; d += e; }
        float inv = 1.f / d;
        for (int i = 0; i < sz; i++) s_alpha[i] *= inv;
    }
    __syncthreads();

    for (int c = tid; c < HID; c += 256) {
        float acc = 0.f;
        for (int i = 0; i < sz; i++)
            acc = fmaf(s_alpha[i], g_H[(size_t)(s0 + i) * PADC + c], acc);
        s_rep[c] = acc;
    }
    __syncthreads();

    for (int rr = w; rr < NREL; rr += 8) {
        float acc = 0.f;
        for (int c = lane; c < HID; c += 32) acc = fmaf(s_rep[c], rel_w[rr * HID + c], acc);
        #pragma unroll
        for (int o = 16; o; o >>= 1) acc += __shfl_xor_sync(0xffffffffu, acc, o);
        if (lane == 0) out[b * NREL + rr] = acc + rel_b[rr];
    }
}

// ---------------- launch ----------------
extern "C" void kernel_launch(void* const* d_in, const int* in_sizes, int n_in,
                              void* d_out, int out_size) {
    const int*   X        = (const int*)  d_in[0];
    const int*   P1       = (const int*)  d_in[1];
    const int*   P2       = (const int*)  d_in[2];
    // d_in[3] mask, d_in[4] length: unused
    const int*   scope    = (const int*)  d_in[5];
    const int*   relation = (const int*)  d_in[6];
    const float* word_emb = (const float*)d_in[7];
    const float* p1e      = (const float*)d_in[8];
    const float* p2e      = (const float*)d_in[9];
    const float* conv_w   = (const float*)d_in[10];
    const float* conv_b   = (const float*)d_in[11];
    const float* rel_w    = (const float*)d_in[12];
    const float* rel_b    = (const float*)d_in[13];
    float* out = (float*)d_out;

    k_prep_Bt<<<(ROWW * KPAD + 255) / 256, 256>>>(conv_w);
    k_pos_tables<<<NPOS, ROWW>>>(p1e, p2e, conv_w);
    k_build_word<<<NROWT, 256>>>(word_emb);
    k_main<<<NSENT / 2, 128>>>(X, P1, P2, conv_b);
    k_bags<<<NBAG, 256>>>(scope, relation, rel_w, rel_b, out);
}

// round 8
// speedup vs baseline: 1.1361x; 1.1361x over previous
#include <cuda_runtime.h>
#include <cuda_fp16.h>

// ---------------- problem constants ----------------
#define NSENT   4000
#define LSEQ    128
#define VOCAB   50002
#define VEC_DIM 50
#define POS_DIM 5
#define EMB     60
#define HID     230
#define PADC    240            // HID padded to 240
#define ROWW    (3*PADC)       // 720 entries per table row (3 kernel taps)
#define ROWB    (ROWW*2)       // row stride in bytes (fp16)
#define KPAD    64             // VEC_DIM padded to 64 for mma (4 k-steps of 16)
#define NCOLT   (ROWW/8)       // 90 col-tiles of 8
#define NROWT   ((VOCAB+15)/16)// 3126 row-tiles of 16
#define SDSTR   728            // s_D row stride in halfs (16B-aligned, conflict-free)
#define NPOS    201
#define NBAG    500
#define NREL    25
#define MAIN_GRID (148*8)      // persistent: one full wave at 8 CTAs/SM

// ---------------- device scratch (static; no runtime allocation) ----------------
__device__ __half g_Bt [ROWW * KPAD];              // B transposed: [720 cols][64 k] fp16
__device__ __half g_Tw [(size_t)VOCAB * ROWW];     // word projection table (fp16, ~72 MB)
__device__ __half g_Tp1[NPOS * ROWW];              // pos1 projection table (fp16)
__device__ __half g_Tp2[NPOS * ROWW];              // pos2 projection table (fp16)
__device__ float  g_H  [NSENT * PADC];             // sentence encodings

// ---------------- helpers ----------------
__device__ __forceinline__ uint2 ldu2b(const char* p) {
    return *reinterpret_cast<const uint2*>(p);
}
__device__ __forceinline__ __half2 h2lo(uint2 u) { return *reinterpret_cast<__half2*>(&u.x); }
__device__ __forceinline__ __half2 h2hi(uint2 u) { return *reinterpret_cast<__half2*>(&u.y); }

// ---------------- kernel 1: build fp16 transposed weight matrix g_Bt ----------------
__global__ void k_prep_Bt(const float* __restrict__ conv_w) {
    int i = blockIdx.x * blockDim.x + threadIdx.x;
    if (i >= ROWW * KPAD) return;
    int n = i >> 6;            // 0..719
    int k = i & 63;
    int tap = n / PADC;
    int c = n - tap * PADC;
    float v = (c < HID && k < VEC_DIM) ? conv_w[(c * EMB + k) * 3 + tap] : 0.f;
    g_Bt[i] = __float2half_rn(v);
}

// ---------------- kernel 2: tiny pos tables (K=5, fp16 out) ----------------
__global__ void k_pos_tables(const float* __restrict__ p1e,
                             const float* __restrict__ p2e,
                             const float* __restrict__ conv_w) {
    int p = blockIdx.x;        // 0..200
    int r = threadIdx.x;       // 0..719
    int k = r / PADC;
    int c = r - k * PADC;
    float a1 = 0.f, a2 = 0.f;
    if (c < HID) {
        #pragma unroll
        for (int e = 0; e < POS_DIM; e++) {
            float w1 = conv_w[(c * EMB + VEC_DIM + e) * 3 + k];
            float w2 = conv_w[(c * EMB + VEC_DIM + POS_DIM + e) * 3 + k];
            a1 = fmaf(p1e[p * POS_DIM + e], w1, a1);
            a2 = fmaf(p2e[p * POS_DIM + e], w2, a2);
        }
    }
    g_Tp1[p * ROWW + r] = __float2half_rn(a1);
    g_Tp2[p * ROWW + r] = __float2half_rn(a2);
}

// ---------------- kernel 3: word table build via mma.sync + smem-staged stores ----------------
__global__ __launch_bounds__(256) void k_build_word(const float* __restrict__ word_emb) {
    __shared__ __half s_A[16 * 66];
    __shared__ __half s_D[16 * SDSTR];              // staged output strip (~23 KB)
    int row0 = blockIdx.x * 16;
    int tid  = threadIdx.x;

    for (int i = tid; i < 16 * 64; i += 256) {
        int r = i >> 6, k = i & 63;
        int gr = row0 + r;
        float v = (gr < VOCAB && k < VEC_DIM) ? word_emb[gr * VEC_DIM + k] : 0.f;
        s_A[r * 66 + k] = __float2half_rn(v);
    }
    __syncthreads();

    int warp = tid >> 5, lane = tid & 31;
    int g = lane >> 2, t = lane & 3;

    unsigned uA[4][4];
    #pragma unroll
    for (int ks = 0; ks < 4; ks++) {
        int k0 = ks * 16;
        uA[ks][0] = *reinterpret_cast<unsigned*>(&s_A[ g      * 66 + k0 + 2*t    ]);
        uA[ks][1] = *reinterpret_cast<unsigned*>(&s_A[(g + 8) * 66 + k0 + 2*t    ]);
        uA[ks][2] = *reinterpret_cast<unsigned*>(&s_A[ g      * 66 + k0 + 2*t + 8]);
        uA[ks][3] = *reinterpret_cast<unsigned*>(&s_A[(g + 8) * 66 + k0 + 2*t + 8]);
    }

    for (int ct = warp; ct < NCOLT; ct += 8) {
        int n0 = ct * 8;
        float c0 = 0.f, c1 = 0.f, c2 = 0.f, c3 = 0.f;
        #pragma unroll
        for (int ks = 0; ks < 4; ks++) {
            int k0 = ks * 16;
            const __half* bp = g_Bt + (n0 + g) * KPAD + k0 + 2*t;
            unsigned b0 = *reinterpret_cast<const unsigned*>(bp);
            unsigned b1 = *reinterpret_cast<const unsigned*>(bp + 8);
            asm volatile(
                "mma.sync.aligned.m16n8k16.row.col.f32.f16.f16.f32 "
                "{%0,%1,%2,%3}, {%4,%5,%6,%7}, {%8,%9}, {%0,%1,%2,%3};"
                : "+f"(c0), "+f"(c1), "+f"(c2), "+f"(c3)
                : "r"(uA[ks][0]), "r"(uA[ks][1]), "r"(uA[ks][2]), "r"(uA[ks][3]),
                  "r"(b0), "r"(b1));
        }
        int col = n0 + 2*t;
        *reinterpret_cast<__half2*>(&s_D[ g      * SDSTR + col]) = __floats2half2_rn(c0, c1);
        *reinterpret_cast<__half2*>(&s_D[(g + 8) * SDSTR + col]) = __floats2half2_rn(c2, c3);
    }
    __syncthreads();

    // coalesced copy-out: 16 rows x 90 uint4 (16B) per row
    int nrow = VOCAB - row0;  if (nrow > 16) nrow = 16;
    for (int i = tid; i < nrow * 90; i += 256) {
        int r = i / 90, u = i - r * 90;
        uint4 val = *reinterpret_cast<uint4*>(&s_D[r * SDSTR + u * 8]);
        *reinterpret_cast<uint4*>(&g_Tw[(size_t)(row0 + r) * ROWW + u * 8]) = val;
    }
}

// ---------------- kernel 4: main fused conv-via-gather + maxpool + relu ----------------
// PERSISTENT grid (one full wave) + half2 math + full 9-load register prefetch
// (R6 structure). block = 128 threads = 2 sentences x 64 lanes.
__global__ __launch_bounds__(128, 8) void k_main(const int* __restrict__ X,
                                                 const int* __restrict__ P1,
                                                 const int* __restrict__ P2,
                                                 const float* __restrict__ conv_b) {
    __shared__ int   s_off[2][3][LSEQ + 1];   // precomputed BYTE offsets (+1 dummy token)
    __shared__ float s_b[PADC];
    int tid = threadIdx.x;
    int grp = tid >> 6, tc = tid & 63;
    int cb = tc * 8;                          // channel byte offset within row

    for (int i = tid; i < PADC; i += 128) s_b[i] = (i < HID) ? conv_b[i] : 0.f;

    for (int pair = blockIdx.x; pair < NSENT / 2; pair += gridDim.x) {
        int sent0 = pair * 2;
        __syncthreads();                      // previous iteration readers done
        for (int i = tid; i < 2 * LSEQ; i += 128) {
            int g = i >> 7, t = i & (LSEQ - 1);
            int s = sent0 + g;
            s_off[g][0][t] = X [s * LSEQ + t] * ROWB;
            s_off[g][1][t] = P1[s * LSEQ + t] * ROWB;
            s_off[g][2][t] = P2[s * LSEQ + t] * ROWB;
        }
        if (tid < 2) {                        // dummy token for prefetch overrun
            s_off[tid][0][LSEQ] = 0;
            s_off[tid][1][LSEQ] = 0;
            s_off[tid][2][LSEQ] = 0;
        }
        __syncthreads();

        if (tc < 60) {
            const int* ow = s_off[grp][0];
            const int* o1 = s_off[grp][1];
            const int* o2 = s_off[grp][2];
            const char* baseW = (const char*)g_Tw  + cb;
            const char* base1 = (const char*)g_Tp1 + cb;
            const char* base2 = (const char*)g_Tp2 + cb;

            __half2 maxA  = __float2half2_rn(-60000.f), maxB = maxA;
            __half2 pendA = __float2half2_rn(-16384.f), pendB = pendA; // absorbs t=0 max
            __half2 prevA = __float2half2_rn(0.f),      prevB = prevA;

            // prologue: load t=0
            const char* rw = baseW + ow[0];
            const char* r1 = base1 + o1[0];
            const char* r2 = base2 + o2[0];
            uint2 w0 = ldu2b(rw);  uint2 w1 = ldu2b(rw + 2*PADC);  uint2 w2 = ldu2b(rw + 4*PADC);
            uint2 q0 = ldu2b(r1);  uint2 q1 = ldu2b(r1 + 2*PADC);  uint2 q2 = ldu2b(r1 + 4*PADC);
            uint2 v0 = ldu2b(r2);  uint2 v1 = ldu2b(r2 + 2*PADC);  uint2 v2 = ldu2b(r2 + 4*PADC);

            #pragma unroll 4
            for (int t = 0; t < LSEQ; t++) {
                // issue ALL loads for t+1 before computing on t
                const char* nw = baseW + ow[t + 1];
                const char* n1 = base1 + o1[t + 1];
                const char* n2 = base2 + o2[t + 1];
                uint2 W0 = ldu2b(nw);  uint2 W1 = ldu2b(nw + 2*PADC);  uint2 W2 = ldu2b(nw + 4*PADC);
                uint2 Q0 = ldu2b(n1);  uint2 Q1 = ldu2b(n1 + 2*PADC);  uint2 Q2 = ldu2b(n1 + 4*PADC);
                uint2 V0 = ldu2b(n2);  uint2 V1 = ldu2b(n2 + 2*PADC);  uint2 V2 = ldu2b(n2 + 4*PADC);

                __half2 a2A = __hadd2(__hadd2(h2lo(w2), h2lo(q2)), h2lo(v2));
                __half2 a2B = __hadd2(__hadd2(h2hi(w2), h2hi(q2)), h2hi(v2));
                maxA = __hmax2(maxA, __hadd2(pendA, a2A));      // h[t-1]
                maxB = __hmax2(maxB, __hadd2(pendB, a2B));
                __half2 a1A = __hadd2(__hadd2(h2lo(w1), h2lo(q1)), h2lo(v1));
                __half2 a1B = __hadd2(__hadd2(h2hi(w1), h2hi(q1)), h2hi(v1));
                pendA = __hadd2(prevA, a1A);
                pendB = __hadd2(prevB, a1B);
                prevA = __hadd2(__hadd2(h2lo(w0), h2lo(q0)), h2lo(v0));
                prevB = __hadd2(__hadd2(h2hi(w0), h2hi(q0)), h2hi(v0));

                w0 = W0; w1 = W1; w2 = W2;
                q0 = Q0; q1 = Q1; q2 = Q2;
                v0 = V0; v1 = V1; v2 = V2;
            }
            maxA = __hmax2(maxA, pendA);      // h[L-1] (a2 of pad token = 0)
            maxB = __hmax2(maxB, pendB);

            float2 mA = __half22float2(maxA);
            float2 mB = __half22float2(maxB);
            int s = sent0 + grp;
            int coff = tc * 4;
            g_H[s * PADC + coff + 0] = fmaxf(mA.x + s_b[coff + 0], 0.f);
            g_H[s * PADC + coff + 1] = fmaxf(mA.y + s_b[coff + 1], 0.f);
            g_H[s * PADC + coff + 2] = fmaxf(mB.x + s_b[coff + 2], 0.f);
            g_H[s * PADC + coff + 3] = fmaxf(mB.y + s_b[coff + 3], 0.f);
        }
    }
}

// ---------------- kernel 5: per-bag softmax attention + classifier ----------------
__global__ __launch_bounds__(256) void k_bags(const int* __restrict__ scope,
                                              const int* __restrict__ relation,
                                              const float* __restrict__ rel_w,
                                              const float* __restrict__ rel_b,
                                              float* __restrict__ out) {
    int b = blockIdx.x;
    __shared__ float s_q[HID];
    __shared__ float s_logit[8];
    __shared__ float s_alpha[8];
    __shared__ float s_rep[HID];

    int tid = threadIdx.x;
    int w = tid >> 5, lane = tid & 31;
    int s0 = scope[2 * b], s1 = scope[2 * b + 1];
    int sz = s1 - s0;
    if (sz > 8) sz = 8;
    int rq = relation[b];

    for (int c = tid; c < HID; c += 256) s_q[c] = rel_w[rq * HID + c];
    __syncthreads();

    if (w < 8) {
        float acc = 0.f;
        if (w < sz) {
            const float* hp = g_H + (size_t)(s0 + w) * PADC;
            for (int c = lane; c < HID; c += 32) acc = fmaf(hp[c], s_q[c], acc);
        }
        #pragma unroll
        for (int o = 16; o; o >>= 1) acc += __shfl_xor_sync(0xffffffffu, acc, o);
        if (lane == 0) s_logit[w] = (w < sz) ? acc : -1e30f;
    }
    __syncthreads();

    if (tid == 0) {
        float m = -1e30f;
        for (int i = 0; i < sz; i++) m = fmaxf(m, s_logit[i]);
        float d = 0.f;
        for (int i = 0; i < sz; i++) { float e = expf(s_logit[i] - m); s_alpha[i] = e; d += e; }
        float inv = 1.f / d;
        for (int i = 0; i < sz; i++) s_alpha[i] *= inv;
    }
    __syncthreads();

    for (int c = tid; c < HID; c += 256) {
        float acc = 0.f;
        for (int i = 0; i < sz; i++)
            acc = fmaf(s_alpha[i], g_H[(size_t)(s0 + i) * PADC + c], acc);
        s_rep[c] = acc;
    }
    __syncthreads();

    for (int rr = w; rr < NREL; rr += 8) {
        float acc = 0.f;
        for (int c = lane; c < HID; c += 32) acc = fmaf(s_rep[c], rel_w[rr * HID + c], acc);
        #pragma unroll
        for (int o = 16; o; o >>= 1) acc += __shfl_xor_sync(0xffffffffu, acc, o);
        if (lane == 0) out[b * NREL + rr] = acc + rel_b[rr];
    }
}

// ---------------- launch ----------------
extern "C" void kernel_launch(void* const* d_in, const int* in_sizes, int n_in,
                              void* d_out, int out_size) {
    const int*   X        = (const int*)  d_in[0];
    const int*   P1       = (const int*)  d_in[1];
    const int*   P2       = (const int*)  d_in[2];
    // d_in[3] mask, d_in[4] length: unused
    const int*   scope    = (const int*)  d_in[5];
    const int*   relation = (const int*)  d_in[6];
    const float* word_emb = (const float*)d_in[7];
    const float* p1e      = (const float*)d_in[8];
    const float* p2e      = (const float*)d_in[9];
    const float* conv_w   = (const float*)d_in[10];
    const float* conv_b   = (const float*)d_in[11];
    const float* rel_w    = (const float*)d_in[12];
    const float* rel_b    = (const float*)d_in[13];
    float* out = (float*)d_out;

    k_prep_Bt<<<(ROWW * KPAD + 255) / 256, 256>>>(conv_w);
    k_pos_tables<<<NPOS, ROWW>>>(p1e, p2e, conv_w);
    k_build_word<<<NROWT, 256>>>(word_emb);
    int mgrid = MAIN_GRID < (NSENT / 2) ? MAIN_GRID : (NSENT / 2);
    k_main<<<mgrid, 128>>>(X, P1, P2, conv_b);
    k_bags<<<NBAG, 256>>>(scope, relation, rel_w, rel_b, out);
}